// round 12
// baseline (speedup 1.0000x reference)
#include <cuda_runtime.h>
#include <cuda_fp16.h>
#include <cstdint>
#include <cstddef>

#define Bsz  64
#define Hd   512
#define Tlen 512
#define G4H  2048
#define Ed   256
#define NCTA 128
#define NTHR 512
#define HB   (Hd * Bsz)

typedef unsigned long long ull;
typedef unsigned u32;

// ---------------- device scratch (static, allowed) ----------------
__device__ __align__(256) float g_xg[(size_t)Tlen * G4H * Bsz];  // 256 MB
__device__ __align__(256) __half g_h0h[2 * HB];   // h0 f16-hi, [parity][b][k]
__device__ __align__(256) __half g_h0l[2 * HB];   // h0 f16-lo
__device__ __align__(256) __half g_h1h[2 * HB];
__device__ __align__(256) __half g_h1l[2 * HB];
__device__ __align__(256) float  g_h1f[HB];       // final fp32 h1 for kclf, [k][b]
__device__ unsigned g_bar1;
__device__ unsigned g_bar2;

// ---------------- packed f32x2 helpers (kA) ----------------
__device__ __forceinline__ ull pk2f(float x) {
    ull r; asm("mov.b64 %0, {%1, %1};" : "=l"(r) : "f"(x)); return r;
}
__device__ __forceinline__ void ffma2(ull& a, ull h, ull w) {
    asm("fma.rn.f32x2 %0, %1, %2, %0;" : "+l"(a) : "l"(h), "l"(w));
}
__device__ __forceinline__ void up2(ull v, float& x, float& y) {
    u32 lo, hi;
    asm("mov.b64 {%0, %1}, %2;" : "=r"(lo), "=r"(hi) : "l"(v));
    x = __uint_as_float(lo); y = __uint_as_float(hi);
}
__device__ __forceinline__ float sigm(float x) {
    return __fdividef(1.f, 1.f + __expf(-x));
}
__device__ __forceinline__ float tanh_fast(float x) {
    float e = __expf(2.f * x);
    return 1.f - __fdividef(2.f, e + 1.f);
}
__device__ __forceinline__ u32 ldcg32(const void* p) {
    u32 v; asm volatile("ld.global.cg.b32 %0, [%1];" : "=r"(v) : "l"(p)); return v;
}
// m16n8k16 f16 mma, fp32 accumulate
__device__ __forceinline__ void mma16(float (&d)[4], u32 a0, u32 a1, u32 a2, u32 a3,
                                      u32 b0, u32 b1) {
    asm("mma.sync.aligned.m16n8k16.row.col.f32.f16.f16.f32 "
        "{%0,%1,%2,%3}, {%4,%5,%6,%7}, {%8,%9}, {%0,%1,%2,%3};"
        : "+f"(d[0]), "+f"(d[1]), "+f"(d[2]), "+f"(d[3])
        : "r"(a0), "r"(a1), "r"(a2), "r"(a3), "r"(b0), "r"(b1));
}

// ---------------- split grid barrier (monotonic) ----------------
__device__ __forceinline__ void bar_arrive(unsigned* ctr) {
    if (threadIdx.x == 0)
        asm volatile("red.release.gpu.global.add.u32 [%0], 1;" :: "l"(ctr) : "memory");
}
__device__ __forceinline__ void bar_wait(unsigned* ctr, unsigned target) {
    if (threadIdx.x == 0) {
        unsigned v;
        do {
            asm volatile("ld.acquire.gpu.global.u32 %0, [%1];" : "=r"(v) : "l"(ctr) : "memory");
        } while (v < target);
    }
    __syncthreads();
}

// =================================================================
// Kernel A (fp32 f32x2, unchanged from R8 — proven)
// =================================================================
__global__ void __launch_bounds__(256) kA(const int* __restrict__ x,
                                          const float* __restrict__ emb,
                                          const float* __restrict__ Wih0,
                                          const float* __restrict__ b0) {
    __shared__ float ws[64 * 33];
    __shared__ float xs2[32 * 66];
    __shared__ int   xr[64];
    const int tid = threadIdx.x;
    const int t   = blockIdx.x;
    const int rb  = blockIdx.y * 64;
    if (tid < 64) xr[tid] = x[tid * Tlen + t];
    __syncthreads();

    ull accA[4], accB[4];
#pragma unroll
    for (int j = 0; j < 4; j++) { accA[j] = 0ull; accB[j] = 0ull; }
    const int r4 = tid >> 4;
    const int q4 = (tid & 15) * 4;

    for (int ec = 0; ec < Ed; ec += 32) {
#pragma unroll
        for (int i = 0; i < 8; i++) {
            int idx = tid + i * 256;
            int a = idx >> 5, e = idx & 31;
            ws[a * 33 + e] = Wih0[(rb + a) * Ed + ec + e];
            xs2[e * 66 + a] = emb[(size_t)xr[a] * Ed + ec + e];
        }
        __syncthreads();
#pragma unroll 8
        for (int e = 0; e < 32; e++) {
            ull x01 = *(const ull*)&xs2[e * 66 + q4];
            ull x23 = *(const ull*)&xs2[e * 66 + q4 + 2];
#pragma unroll
            for (int j = 0; j < 4; j++) {
                ull w2 = pk2f(ws[(r4 * 4 + j) * 33 + e]);
                ffma2(accA[j], x01, w2);
                ffma2(accB[j], x23, w2);
            }
        }
        __syncthreads();
    }
#pragma unroll
    for (int j = 0; j < 4; j++) {
        int row = rb + r4 * 4 + j;
        float bv = b0[row];
        float4 o;
        up2(accA[j], o.x, o.y);
        up2(accB[j], o.z, o.w);
        o.x += bv; o.y += bv; o.z += bv; o.w += bv;
        *(float4*)(g_xg + ((size_t)t * G4H + row) * Bsz + q4) = o;
    }
}

// =================================================================
__global__ void kzero() {
    int i = blockIdx.x * 256 + threadIdx.x;   // grid 256 -> 65536 = 2*HB
    g_h0h[i] = __ushort_as_half(0);
    g_h0l[i] = __ushort_as_half(0);
    g_h1h[i] = __ushort_as_half(0);
    g_h1l[i] = __ushort_as_half(0);
    if (i == 0) { g_bar1 = 0u; g_bar2 = 0u; }
}

// =================================================================
// Persistent recurrent kernel: R8 schedule, f16 hi/lo 3-pass mma.sync.
// 128 CTAs x 512 threads; warp = (nt 0..7 batch-tile, kh 0..1 k-half).
// CTA owns 16 gate rows (j: j&3=gate, j>>2=unit) = one m16 tile.
// smem: fragH (96 chunks x 32 lanes x 8 halves) | fragL | pbuf[2][16][66]
// =================================================================
#define FRAGH_OFF 0
#define FRAGL_OFF 49152
#define PBUF_OFF  98304
#define SMEMB     (98304 + 2 * 16 * 66 * 4)

// stage one 16x512 weight tile as packed per-lane f16 hi/lo A-fragments
__device__ void stage16(const float* __restrict__ W, __half* fH, __half* fL,
                        int u0, int chunkbase) {
    for (int idx = threadIdx.x; idx < 16 * 512; idx += NTHR) {
        int j = idx >> 9, k = idx & 511;
        int grow = ((j & 3) << 9) + u0 + (j >> 2);
        float w = W[grow * Hd + k];
        __half hi = __float2half_rn(w);
        __half lo = __float2half_rn(w - __half2float(hi));
        int ci   = chunkbase + (k >> 4);
        int lane = ((j & 7) << 2) + ((k & 7) >> 1);
        int hf   = (((k >> 3) & 1) << 2) + ((j >> 3) << 1) + (k & 1);
        int addr = (ci * 32 + lane) * 8 + hf;
        fH[addr] = hi;
        fL[addr] = lo;
    }
}

// one 256-k slice: 16 k16-iters of 3-pass f16 mma
__device__ __forceinline__ void mma_slice16(float (&d)[4], const __half* fH,
                                            const __half* fL, int chunk0,
                                            const __half* bh, const __half* bl,
                                            int boff, int lane) {
    u32 rb[4][4];
#pragma unroll
    for (int j = 0; j < 4; j++) {
        const __half* p0 = bh + boff + j * 16;
        const __half* p1 = bl + boff + j * 16;
        rb[j][0] = ldcg32(p0);     rb[j][1] = ldcg32(p0 + 8);
        rb[j][2] = ldcg32(p1);     rb[j][3] = ldcg32(p1 + 8);
    }
#pragma unroll
    for (int i = 0; i < 16; i++) {
        u32 b0h = rb[i & 3][0], b1h = rb[i & 3][1];
        u32 b0l = rb[i & 3][2], b1l = rb[i & 3][3];
        if (i + 4 < 16) {
            const __half* p0 = bh + boff + (i + 4) * 16;
            const __half* p1 = bl + boff + (i + 4) * 16;
            rb[i & 3][0] = ldcg32(p0);     rb[i & 3][1] = ldcg32(p0 + 8);
            rb[i & 3][2] = ldcg32(p1);     rb[i & 3][3] = ldcg32(p1 + 8);
        }
        uint4 ah = *(const uint4*)(fH + ((size_t)(chunk0 + i) * 32 + lane) * 8);
        uint4 al = *(const uint4*)(fL + ((size_t)(chunk0 + i) * 32 + lane) * 8);
        mma16(d, ah.x, ah.y, ah.z, ah.w, b0h, b1h);
        mma16(d, ah.x, ah.y, ah.z, ah.w, b0l, b1l);
        mma16(d, al.x, al.y, al.z, al.w, b0h, b1h);
    }
}

__global__ void __launch_bounds__(NTHR, 1) lstm_rec(const float* __restrict__ Whh0,
                                                    const float* __restrict__ Wih1,
                                                    const float* __restrict__ Whh1,
                                                    const float* __restrict__ b1) {
    extern __shared__ char smem[];
    __half* fH   = (__half*)(smem + FRAGH_OFF);
    __half* fL   = (__half*)(smem + FRAGL_OFF);
    float*  pbuf = (float*)(smem + PBUF_OFF);

    const int tid = threadIdx.x;
    const int u0  = blockIdx.x * 4;

    stage16(Whh0, fH, fL, u0, 0);     // chunks  0..31
    stage16(Wih1, fH, fL, u0, 32);    // chunks 32..63
    stage16(Whh1, fH, fL, u0, 64);    // chunks 64..95
    __syncthreads();

    // mma role
    const int w    = tid >> 5;
    const int nt   = w & 7;
    const int kh   = w >> 3;
    const int lane = tid & 31;
    const int gid  = lane >> 2;
    const int tig  = lane & 3;
    const int n    = nt * 8 + gid;
    const int boff = n * 512 + kh * 256 + tig * 2;
    const int ch   = kh * 16;
    // update role (tid < 256)
    const int uu = tid >> 6;
    const int bb = tid & 63;
    const int hidx = bb * 512 + u0 + uu;    // [b][k] slot this thread owns
    float c0 = 0.f, c1 = 0.f;
    float b1v[4] = {0.f, 0.f, 0.f, 0.f};
    if (tid < 256)
#pragma unroll
        for (int g = 0; g < 4; g++) b1v[g] = b1[(g << 9) + u0 + uu];

    for (int t = 0; t < Tlen; t++) {
        const int p = t & 1;

        float xgv[4] = {0.f, 0.f, 0.f, 0.f};
        if (tid < 256)
#pragma unroll
            for (int g = 0; g < 4; g++)
                xgv[g] = __ldcs(&g_xg[((size_t)t * G4H + (g << 9) + u0 + uu) * Bsz + bb]);

        // ========== phase 1: gates0 partials = Whh0[:, kslice] @ h0_prev ==========
        {
            float d1[4] = {0.f, 0.f, 0.f, 0.f};
            mma_slice16(d1, fH, fL, 0 + ch, g_h0h + (p ^ 1) * HB, g_h0l + (p ^ 1) * HB,
                        boff, lane);
            *(float2*)&pbuf[(kh * 16 + gid) * 66 + nt * 8 + 2 * tig]     = make_float2(d1[0], d1[1]);
            *(float2*)&pbuf[(kh * 16 + gid + 8) * 66 + nt * 8 + 2 * tig] = make_float2(d1[2], d1[3]);
        }
        __syncthreads();
        if (tid < 256) {
            float s[4];
#pragma unroll
            for (int g = 0; g < 4; g++) {
                int r = uu * 4 + g;
                s[g] = xgv[g] + pbuf[r * 66 + bb] + pbuf[(16 + r) * 66 + bb];
            }
            c0 = sigm(s[1]) * c0 + sigm(s[0]) * tanh_fast(s[2]);
            float h0n = sigm(s[3]) * tanh_fast(c0);
            __half hi = __float2half_rn(h0n);
            g_h0h[p * HB + hidx] = hi;
            g_h0l[p * HB + hidx] = __float2half_rn(h0n - __half2float(hi));
        }
        __syncthreads();
        bar_arrive(&g_bar1);           // publish h0(t)

        // ========== phase 2: Whh1 @ h1_prev, then Wih1 @ h0n ==========
        float d2[4] = {0.f, 0.f, 0.f, 0.f};
        bar_wait(&g_bar2, NCTA * (unsigned)t);
        mma_slice16(d2, fH, fL, 64 + ch, g_h1h + (p ^ 1) * HB, g_h1l + (p ^ 1) * HB,
                    boff, lane);
        bar_wait(&g_bar1, NCTA * (unsigned)(t + 1));
        mma_slice16(d2, fH, fL, 32 + ch, g_h0h + p * HB, g_h0l + p * HB,
                    boff, lane);
        *(float2*)&pbuf[(kh * 16 + gid) * 66 + nt * 8 + 2 * tig]     = make_float2(d2[0], d2[1]);
        *(float2*)&pbuf[(kh * 16 + gid + 8) * 66 + nt * 8 + 2 * tig] = make_float2(d2[2], d2[3]);

        __syncthreads();
        if (tid < 256) {
            float s[4];
#pragma unroll
            for (int g = 0; g < 4; g++) {
                int r = uu * 4 + g;
                s[g] = b1v[g] + pbuf[r * 66 + bb] + pbuf[(16 + r) * 66 + bb];
            }
            c1 = sigm(s[1]) * c1 + sigm(s[0]) * tanh_fast(s[2]);
            float h1n = sigm(s[3]) * tanh_fast(c1);
            __half hi = __float2half_rn(h1n);
            g_h1h[p * HB + hidx] = hi;
            g_h1l[p * HB + hidx] = __float2half_rn(h1n - __half2float(hi));
            if (t == Tlen - 1)
                g_h1f[(u0 + uu) * 64 + bb] = h1n;
        }
        __syncthreads();
        bar_arrive(&g_bar2);           // publish h1(t)
    }
}

// =================================================================
// classifier (reads g_h1f [k][b])
// =================================================================
__global__ void __launch_bounds__(1024) kclf(const float* __restrict__ Wclf,
                                             const float* __restrict__ bclf,
                                             float* __restrict__ out) {
    __shared__ float red[1024];
    const int t  = threadIdx.x;
    const int o  = t & 1;
    const int b  = (t >> 1) & 63;
    const int ks = t >> 7;
    const float* h = g_h1f;
    float s = 0.f;
#pragma unroll 8
    for (int i = 0; i < 64; i++) {
        int k = ks * 64 + i;
        s = fmaf(Wclf[o * Hd + k], h[k * 64 + b], s);
    }
    red[t] = s;
    __syncthreads();
    if (ks == 0) {
        float v = s + bclf[o];
#pragma unroll
        for (int w8 = 1; w8 < 8; w8++) v += red[t + w8 * 128];
        out[b * 2 + o] = v;
    }
}

// =================================================================
extern "C" void kernel_launch(void* const* d_in, const int* in_sizes, int n_in,
                              void* d_out, int out_size) {
    const int*   x    = (const int*)  d_in[0];
    const float* emb  = (const float*)d_in[1];
    const float* Wih0 = (const float*)d_in[2];
    const float* Whh0 = (const float*)d_in[3];
    const float* b0   = (const float*)d_in[4];
    const float* Wih1 = (const float*)d_in[5];
    const float* Whh1 = (const float*)d_in[6];
    const float* b1   = (const float*)d_in[7];
    const float* Wclf = (const float*)d_in[8];
    const float* bclf = (const float*)d_in[9];
    float* out = (float*)d_out;

    cudaFuncSetAttribute(lstm_rec, cudaFuncAttributeMaxDynamicSharedMemorySize, SMEMB);

    kzero<<<256, 256>>>();
    dim3 gA(Tlen, 32);
    kA<<<gA, 256>>>(x, emb, Wih0, b0);
    lstm_rec<<<NCTA, NTHR, SMEMB>>>(Whh0, Wih1, Whh1, b1);
    kclf<<<1, 1024>>>(Wclf, bclf, out);
}

// round 13
// speedup vs baseline: 1.4362x; 1.4362x over previous
#include <cuda_runtime.h>
#include <cstdint>
#include <cstddef>

#define Bsz   64
#define Hd    512
#define Tlen  512
#define G4H   2048
#define Ed    256
#define NMAIN 128
#define NHELP 16
#define NCTA  (NMAIN + NHELP)
#define NTHR  512
#define HB    (Hd * Bsz)
#define PPAD  18

typedef unsigned long long ull;

// ---------------- device scratch (static, allowed) ----------------
__device__ __align__(256) float g_xg[(size_t)Tlen * G4H * Bsz];  // 256 MB
__device__ __align__(256) float g_h0[2 * HB];
__device__ __align__(256) float g_h1[2 * HB];
__device__ __align__(256) float g_hp1[NMAIN * 1024];   // helper P1 partials [main][row16][b]
__device__ __align__(256) float g_hp2[NMAIN * 1024];   // helper P2 partials
__device__ unsigned g_bar1;
__device__ unsigned g_bar2;
__device__ unsigned g_cnt1;   // helper P1 arrivals
__device__ unsigned g_cnt2;   // helper P2 arrivals

// ---------------- packed f32x2 helpers ----------------
__device__ __forceinline__ ull pk2f(float x) {
    ull r; asm("mov.b64 %0, {%1, %1};" : "=l"(r) : "f"(x)); return r;
}
__device__ __forceinline__ ull pk2(float x, float y) {
    ull r; asm("mov.b64 %0, {%1, %2};" : "=l"(r) : "f"(x), "f"(y)); return r;
}
__device__ __forceinline__ void ffma2(ull& a, ull h, ull w) {
    asm("fma.rn.f32x2 %0, %1, %2, %0;" : "+l"(a) : "l"(h), "l"(w));
}
__device__ __forceinline__ void up2(ull v, float& x, float& y) {
    unsigned lo, hi;
    asm("mov.b64 {%0, %1}, %2;" : "=r"(lo), "=r"(hi) : "l"(v));
    x = __uint_as_float(lo); y = __uint_as_float(hi);
}
__device__ __forceinline__ float sigm(float x) {
    return __fdividef(1.f, 1.f + __expf(-x));
}
__device__ __forceinline__ float tanh_fast(float x) {
    float e = __expf(2.f * x);
    return 1.f - __fdividef(2.f, e + 1.f);
}

// ---------------- split grid barriers (monotonic counters) ----------------
__device__ __forceinline__ void bar_arrive(unsigned* ctr) {
    if (threadIdx.x == 0)
        asm volatile("red.release.gpu.global.add.u32 [%0], 1;" :: "l"(ctr) : "memory");
}
__device__ __forceinline__ void bar_wait(unsigned* ctr, unsigned target) {
    if (threadIdx.x == 0) {
        unsigned v;
        do {
            asm volatile("ld.acquire.gpu.global.u32 %0, [%1];" : "=r"(v) : "l"(ctr) : "memory");
        } while (v < target);
    }
    __syncthreads();
}

// =================================================================
// Kernel A (fp32 f32x2, unchanged — proven)
// =================================================================
__global__ void __launch_bounds__(256) kA(const int* __restrict__ x,
                                          const float* __restrict__ emb,
                                          const float* __restrict__ Wih0,
                                          const float* __restrict__ b0) {
    __shared__ float ws[64 * 33];
    __shared__ float xs2[32 * 66];
    __shared__ int   xr[64];
    const int tid = threadIdx.x;
    const int t   = blockIdx.x;
    const int rb  = blockIdx.y * 64;
    if (tid < 64) xr[tid] = x[tid * Tlen + t];
    __syncthreads();

    ull accA[4], accB[4];
#pragma unroll
    for (int j = 0; j < 4; j++) { accA[j] = 0ull; accB[j] = 0ull; }
    const int r4 = tid >> 4;
    const int q4 = (tid & 15) * 4;

    for (int ec = 0; ec < Ed; ec += 32) {
#pragma unroll
        for (int i = 0; i < 8; i++) {
            int idx = tid + i * 256;
            int a = idx >> 5, e = idx & 31;
            ws[a * 33 + e] = Wih0[(rb + a) * Ed + ec + e];
            xs2[e * 66 + a] = emb[(size_t)xr[a] * Ed + ec + e];
        }
        __syncthreads();
#pragma unroll 8
        for (int e = 0; e < 32; e++) {
            ull x01 = *(const ull*)&xs2[e * 66 + q4];
            ull x23 = *(const ull*)&xs2[e * 66 + q4 + 2];
#pragma unroll
            for (int j = 0; j < 4; j++) {
                ull w2 = pk2f(ws[(r4 * 4 + j) * 33 + e]);
                ffma2(accA[j], x01, w2);
                ffma2(accB[j], x23, w2);
            }
        }
        __syncthreads();
    }
#pragma unroll
    for (int j = 0; j < 4; j++) {
        int row = rb + r4 * 4 + j;
        float bv = b0[row];
        float4 o;
        up2(accA[j], o.x, o.y);
        up2(accB[j], o.z, o.w);
        o.x += bv; o.y += bv; o.z += bv; o.w += bv;
        *(float4*)(g_xg + ((size_t)t * G4H + row) * Bsz + q4) = o;
    }
}

// =================================================================
__global__ void kzero() {
    int i = blockIdx.x * 256 + threadIdx.x;   // grid 256 -> 65536 = 2*HB
    g_h0[i] = 0.f;
    g_h1[i] = 0.f;
    if (i == 0) { g_bar1 = 0u; g_bar2 = 0u; g_cnt1 = 0u; g_cnt2 = 0u; }
}

// =================================================================
// Main K-splits (warp-uniform): P1 K=480 (NK 30) | P2B(Whh1) 432 (27)
// | P2A(Wih1) 464 (29). Helpers cover tails 32/80/48 for 8 mains each.
// main smem: wT0 7680f | wT1ih 7424f | wT1hh 6912f | pbuf 18432f
// helper smem: whs 128 rows x 160 floats
// =================================================================
#define K0M  480
#define K2BM 432
#define K2AM 464
#define MW0   0
#define MW1I  7680
#define MW1H  15104
#define MPB   22016
#define SMTOTF 40448
#define SMEMB  (SMTOTF * 4)

template <int NK>
__device__ __forceinline__ void gemm2(ull (&acc)[4][4], const float* wT, int kw0,
                                      const float* __restrict__ hsrc, int kh0,
                                      int rh, int q) {
    const float4* hp = (const float4*)hsrc + q;
    float4 hbuf[8];
#pragma unroll
    for (int j = 0; j < 8; j++) hbuf[j] = __ldcg(hp + (size_t)(kh0 + j) * 16);
#pragma unroll 8
    for (int i = 0; i < NK; i++) {
        float4 hc = hbuf[i & 7];
        if (i + 8 < NK) hbuf[i & 7] = __ldcg(hp + (size_t)(kh0 + i + 8) * 16);
        const ulonglong2* wp = (const ulonglong2*)(wT + (kw0 + i) * 16 + rh * 8);
        ulonglong2 wa = wp[0];
        ulonglong2 wb = wp[1];
        ull h2;
        h2 = pk2f(hc.x);
        ffma2(acc[0][0], wa.x, h2); ffma2(acc[1][0], wa.y, h2);
        ffma2(acc[2][0], wb.x, h2); ffma2(acc[3][0], wb.y, h2);
        h2 = pk2f(hc.y);
        ffma2(acc[0][1], wa.x, h2); ffma2(acc[1][1], wa.y, h2);
        ffma2(acc[2][1], wb.x, h2); ffma2(acc[3][1], wb.y, h2);
        h2 = pk2f(hc.z);
        ffma2(acc[0][2], wa.x, h2); ffma2(acc[1][2], wa.y, h2);
        ffma2(acc[2][2], wb.x, h2); ffma2(acc[3][2], wb.y, h2);
        h2 = pk2f(hc.w);
        ffma2(acc[0][3], wa.x, h2); ffma2(acc[1][3], wa.y, h2);
        ffma2(acc[2][3], wb.x, h2); ffma2(acc[3][3], wb.y, h2);
    }
}

__device__ __forceinline__ void storep(float* pbuf, ull (&acc)[4][4],
                                       int w, int rh, int q) {
#pragma unroll
    for (int p = 0; p < 4; p++)
#pragma unroll
        for (int j = 0; j < 4; j++)
            *(ull*)&pbuf[(w * 64 + q * 4 + j) * PPAD + rh * 8 + 2 * p] = acc[p][j];
}

// helper gemm: 8 rows (one per main) x 2 batches/lane over NK tail-k's
template <int NK>
__device__ __forceinline__ void hgemm(ull (&a)[8], const float* wbase,
                                      const float* __restrict__ hsrc, int lane) {
    const float2* hp = (const float2*)hsrc + lane;   // 32 float2 per k-row
    float2 ring[4];
#pragma unroll
    for (int j = 0; j < 4; j++) ring[j] = __ldcg(hp + (size_t)j * 32);
#pragma unroll 4
    for (int i = 0; i < NK; i++) {
        float2 hc = ring[i & 3];
        if (i + 4 < NK) ring[i & 3] = __ldcg(hp + (size_t)(i + 4) * 32);
        ull h2 = pk2(hc.x, hc.y);
        const float* wp = wbase + i;
#pragma unroll
        for (int j = 0; j < 8; j++)
            ffma2(a[j], h2, pk2f(wp[j * 160]));
    }
}

__global__ void __launch_bounds__(NTHR, 1) lstm_rec(const float* __restrict__ Whh0,
                                                    const float* __restrict__ Wih1,
                                                    const float* __restrict__ Whh1,
                                                    const float* __restrict__ b1) {
    extern __shared__ float sm[];
    const int tid = threadIdx.x;

    if (blockIdx.x < NMAIN) {
        // ===================== MAIN CTA =====================
        float* wT0  = sm + MW0;
        float* wT1i = sm + MW1I;
        float* wT1h = sm + MW1H;
        float* pbuf = sm + MPB;
        const int u0 = blockIdx.x * 4;

        for (int idx = tid; idx < K0M * 16; idx += NTHR) {
            int k = idx >> 4, j = idx & 15;
            int row = ((j & 3) << 9) + u0 + (j >> 2);
            wT0[idx] = Whh0[row * Hd + k];
        }
        for (int idx = tid; idx < K2AM * 16; idx += NTHR) {
            int k = idx >> 4, j = idx & 15;
            int row = ((j & 3) << 9) + u0 + (j >> 2);
            wT1i[idx] = Wih1[row * Hd + k];
        }
        for (int idx = tid; idx < K2BM * 16; idx += NTHR) {
            int k = idx >> 4, j = idx & 15;
            int row = ((j & 3) << 9) + u0 + (j >> 2);
            wT1h[idx] = Whh1[row * Hd + k];
        }
        __syncthreads();

        const int w    = tid >> 5;
        const int lane = tid & 31;
        const int rh   = lane >> 4;
        const int q    = lane & 15;
        const int uu   = tid >> 6;
        const int bb   = tid & 63;
        float c0 = 0.f, c1 = 0.f;
        float b1v[4] = {0.f, 0.f, 0.f, 0.f};
        if (tid < 256)
#pragma unroll
            for (int g = 0; g < 4; g++) b1v[g] = b1[(g << 9) + u0 + uu];

        for (int t = 0; t < Tlen; t++) {
            const int p = t & 1;

            float xgv[4] = {0.f, 0.f, 0.f, 0.f};
            if (tid < 256)
#pragma unroll
                for (int g = 0; g < 4; g++)
                    xgv[g] = __ldcs(&g_xg[((size_t)t * G4H + (g << 9) + u0 + uu) * Bsz + bb]);

            // ---- phase 1 ----
            {
                ull acc[4][4];
#pragma unroll
                for (int a = 0; a < 4; a++)
#pragma unroll
                    for (int b = 0; b < 4; b++) acc[a][b] = 0ull;
                gemm2<30>(acc, wT0, w * 30, g_h0 + (p ^ 1) * HB, w * 30, rh, q);
                storep(pbuf, acc, w, rh, q);
            }
            __syncthreads();
            bar_wait(&g_cnt1, NHELP * (unsigned)(t + 1));   // helper P1 partials ready
            if (tid < 256) {
                float hpv[4];
#pragma unroll
                for (int g = 0; g < 4; g++)
                    hpv[g] = __ldcg(&g_hp1[blockIdx.x * 1024 + (uu * 4 + g) * 64 + bb]);
                float s[4];
#pragma unroll
                for (int g = 0; g < 4; g++) s[g] = xgv[g] + hpv[g];
#pragma unroll
                for (int w16 = 0; w16 < 16; w16++) {
                    const float* pp = &pbuf[(w16 * 64 + bb) * PPAD + uu * 4];
                    float2 v0 = *(const float2*)pp;
                    float2 v1 = *(const float2*)(pp + 2);
                    s[0] += v0.x; s[1] += v0.y; s[2] += v1.x; s[3] += v1.y;
                }
                c0 = sigm(s[1]) * c0 + sigm(s[0]) * tanh_fast(s[2]);
                float h0n = sigm(s[3]) * tanh_fast(c0);
                g_h0[p * HB + (u0 + uu) * 64 + bb] = h0n;
            }
            __syncthreads();
            bar_arrive(&g_bar1);           // publish h0(t)

            // ---- phase 2 ----
            ull acc2[4][4];
#pragma unroll
            for (int a = 0; a < 4; a++)
#pragma unroll
                for (int b = 0; b < 4; b++) acc2[a][b] = 0ull;

            bar_wait(&g_bar2, NMAIN * (unsigned)t);
            gemm2<27>(acc2, wT1h, w * 27, g_h1 + (p ^ 1) * HB, w * 27, rh, q);
            bar_wait(&g_bar1, NMAIN * (unsigned)(t + 1));
            gemm2<29>(acc2, wT1i, w * 29, g_h0 + p * HB, w * 29, rh, q);
            storep(pbuf, acc2, w, rh, q);

            __syncthreads();
            bar_wait(&g_cnt2, NHELP * (unsigned)(t + 1));
            if (tid < 256) {
                float hpv[4];
#pragma unroll
                for (int g = 0; g < 4; g++)
                    hpv[g] = __ldcg(&g_hp2[blockIdx.x * 1024 + (uu * 4 + g) * 64 + bb]);
                float s[4];
#pragma unroll
                for (int g = 0; g < 4; g++) s[g] = b1v[g] + hpv[g];
#pragma unroll
                for (int w16 = 0; w16 < 16; w16++) {
                    const float* pp = &pbuf[(w16 * 64 + bb) * PPAD + uu * 4];
                    float2 v0 = *(const float2*)pp;
                    float2 v1 = *(const float2*)(pp + 2);
                    s[0] += v0.x; s[1] += v0.y; s[2] += v1.x; s[3] += v1.y;
                }
                c1 = sigm(s[1]) * c1 + sigm(s[0]) * tanh_fast(s[2]);
                float h1n = sigm(s[3]) * tanh_fast(c1);
                g_h1[p * HB + (u0 + uu) * 64 + bb] = h1n;
            }
            __syncthreads();
            bar_arrive(&g_bar2);           // publish h1(t)
        }
    } else {
        // ===================== HELPER CTA =====================
        float* whs = sm;                   // [128 rows][160 k-tail floats]
        const int hid = blockIdx.x - NMAIN;
        const int mb  = hid * 8;           // serves mains mb..mb+7

        for (int idx = tid; idx < 128 * 160; idx += NTHR) {
            int wrow = idx / (8 * 160);
            int j    = (idx / 160) & 7;
            int kl   = idx % 160;
            int m    = mb + j;
            int grow = ((wrow & 3) << 9) + m * 4 + (wrow >> 2);
            float v;
            if (kl < 32)       v = Whh0[grow * Hd + 480 + kl];
            else if (kl < 112) v = Whh1[grow * Hd + 432 + (kl - 32)];
            else               v = Wih1[grow * Hd + 464 + (kl - 112)];
            whs[idx] = v;
        }
        __syncthreads();

        const int w    = tid >> 5;        // warp = local row 0..15
        const int lane = tid & 31;        // lane -> batches 2l, 2l+1
        const float* wb = whs + (w * 8) * 160;

        for (int t = 0; t < Tlen; t++) {
            const int p = t & 1;

            // ---- P1 tail: Whh0[:, 480:512) @ h0(t-1) ----
            bar_wait(&g_bar1, NMAIN * (unsigned)t);
            ull a1[8];
#pragma unroll
            for (int j = 0; j < 8; j++) a1[j] = 0ull;
            hgemm<32>(a1, wb + 0, g_h0 + (p ^ 1) * HB + 480 * 64, lane);
#pragma unroll
            for (int j = 0; j < 8; j++) {
                float2 v; up2(a1[j], v.x, v.y);
                *(float2*)&g_hp1[(mb + j) * 1024 + w * 64 + 2 * lane] = v;
            }
            __syncthreads();
            bar_arrive(&g_cnt1);

            // ---- P2 tails: Whh1[:, 432:512) @ h1(t-1), Wih1[:, 464:512) @ h0(t) ----
            ull a2[8];
#pragma unroll
            for (int j = 0; j < 8; j++) a2[j] = 0ull;
            bar_wait(&g_bar2, NMAIN * (unsigned)t);
            hgemm<80>(a2, wb + 32, g_h1 + (p ^ 1) * HB + 432 * 64, lane);
            bar_wait(&g_bar1, NMAIN * (unsigned)(t + 1));
            hgemm<48>(a2, wb + 112, g_h0 + p * HB + 464 * 64, lane);
#pragma unroll
            for (int j = 0; j < 8; j++) {
                float2 v; up2(a2[j], v.x, v.y);
                *(float2*)&g_hp2[(mb + j) * 1024 + w * 64 + 2 * lane] = v;
            }
            __syncthreads();
            bar_arrive(&g_cnt2);
        }
    }
}

// =================================================================
__global__ void __launch_bounds__(1024) kclf(const float* __restrict__ Wclf,
                                             const float* __restrict__ bclf,
                                             float* __restrict__ out) {
    __shared__ float red[1024];
    const int t  = threadIdx.x;
    const int o  = t & 1;
    const int b  = (t >> 1) & 63;
    const int ks = t >> 7;
    const float* h = g_h1 + HB;       // t=511 parity 1
    float s = 0.f;
#pragma unroll 8
    for (int i = 0; i < 64; i++) {
        int k = ks * 64 + i;
        s = fmaf(Wclf[o * Hd + k], h[k * 64 + b], s);
    }
    red[t] = s;
    __syncthreads();
    if (ks == 0) {
        float v = s + bclf[o];
#pragma unroll
        for (int w8 = 1; w8 < 8; w8++) v += red[t + w8 * 128];
        out[b * 2 + o] = v;
    }
}

// =================================================================
extern "C" void kernel_launch(void* const* d_in, const int* in_sizes, int n_in,
                              void* d_out, int out_size) {
    const int*   x    = (const int*)  d_in[0];
    const float* emb  = (const float*)d_in[1];
    const float* Wih0 = (const float*)d_in[2];
    const float* Whh0 = (const float*)d_in[3];
    const float* b0   = (const float*)d_in[4];
    const float* Wih1 = (const float*)d_in[5];
    const float* Whh1 = (const float*)d_in[6];
    const float* b1   = (const float*)d_in[7];
    const float* Wclf = (const float*)d_in[8];
    const float* bclf = (const float*)d_in[9];
    float* out = (float*)d_out;

    cudaFuncSetAttribute(lstm_rec, cudaFuncAttributeMaxDynamicSharedMemorySize, SMEMB);

    kzero<<<256, 256>>>();
    dim3 gA(Tlen, 32);
    kA<<<gA, 256>>>(x, emb, Wih0, b0);
    lstm_rec<<<NCTA, NTHR, SMEMB>>>(Whh0, Wih1, Whh1, b1);
    kclf<<<1, 1024>>>(Wclf, bclf, out);
}